// round 4
// baseline (speedup 1.0000x reference)
#include <cuda_runtime.h>

#define WTH 256

// ---------------- filter constants (db4-style reconstruction filters) -------
#define LO0f ( 0.23037781330885523f)
#define LO1f ( 0.7148465705525415f)
#define LO2f ( 0.6308807679295904f)
#define LO3f (-0.02798376941698385f)
#define LO4f (-0.18703481171888114f)
#define LO5f ( 0.030841381835986965f)
#define LO6f ( 0.032883011666982945f)
#define LO7f (-0.010597401784997278f)
// hi[i] = lo[7-i] * (i odd ? -1 : +1)
#define HI0f (-0.010597401784997278f)
#define HI1f (-0.032883011666982945f)
#define HI2f ( 0.030841381835986965f)
#define HI3f ( 0.18703481171888114f)
#define HI4f (-0.02798376941698385f)
#define HI5f (-0.6308807679295904f)
#define HI6f ( 0.7148465705525415f)
#define HI7f (-0.23037781330885523f)

// approximation lengths per level; cd length at level l is c_NA[l]
__constant__ int c_NA[10]  = {4096, 2051, 1029, 518, 262, 134, 70, 38, 22, 14};
// offsets of cds[l-1] inside the packed smem cds array (total 4138 floats)
__constant__ int c_OFF[9]  = {0, 2051, 3080, 3598, 3860, 3994, 4064, 4102, 4124};

// ---------------- scratch (device globals; no runtime allocation) -----------
__device__ __align__(16) float g_h[2048UL * 32768UL];      // relu(wavelet feats)
__device__ __align__(16) float g_part[4][2048 * 181];      // split-K partials

// ---------------- DWT stage: src[n] -> ca[m], cd[m] -------------------------
__device__ __forceinline__ void dwt_stage(const float* __restrict__ src, int n,
                                          float* __restrict__ ca,
                                          float* __restrict__ cd, int m)
{
    const float LO[8] = {LO0f, LO1f, LO2f, LO3f, LO4f, LO5f, LO6f, LO7f};
    const float HI[8] = {HI0f, HI1f, HI2f, HI3f, HI4f, HI5f, HI6f, HI7f};
    for (int k = threadIdx.x; k < m; k += WTH) {
        int base = 2 * k;
        float alo = 0.0f, ahi = 0.0f;
        if (base >= 6 && base <= n - 2) {           // all 8 taps interior
            const float* p = src + base - 6;
            #pragma unroll
            for (int t = 0; t < 8; ++t) {
                float v = p[t];
                alo = fmaf(v, LO[t], alo);
                ahi = fmaf(v, HI[t], ahi);
            }
        } else {                                    // symmetric-ext boundary
            #pragma unroll
            for (int t = 0; t < 8; ++t) {
                int idx = base + t;
                int e = (idx < 6) ? (5 - idx)
                                  : ((idx < n + 6) ? (idx - 6) : (2 * n + 5 - idx));
                float v = src[e];
                alo = fmaf(v, LO[t], alo);
                ahi = fmaf(v, HI[t], ahi);
            }
        }
        ca[k] = alo;
        cd[k] = ahi;
    }
}

// ---------------- IDWT stage: (ca[n], cd[n]) -> out[2n-6] -------------------
// out[2u]   = ca[u+3]*LO0 + ca[u+2]*LO2 + ca[u+1]*LO4 + ca[u]*LO6 (+ HI terms)
// out[2u+1] = ca[u+3]*LO1 + ca[u+2]*LO3 + ca[u+1]*LO5 + ca[u]*LO7 (+ HI terms)
template <bool HAS_CA, bool HAS_CD, bool FINAL>
__device__ __forceinline__ void idwt_stage(const float* __restrict__ ca,
                                           const float* __restrict__ cd,
                                           int n, float* __restrict__ out)
{
    int half = n - 3;   // output length = 2n-6 = 2*half
    for (int u = threadIdx.x; u < half; u += WTH) {
        float ev = 0.0f, od = 0.0f;
        if (HAS_CA) {
            float a0 = ca[u], a1 = ca[u + 1], a2 = ca[u + 2], a3 = ca[u + 3];
            ev = fmaf(a3, LO0f, fmaf(a2, LO2f, fmaf(a1, LO4f, a0 * LO6f)));
            od = fmaf(a3, LO1f, fmaf(a2, LO3f, fmaf(a1, LO5f, a0 * LO7f)));
        }
        if (HAS_CD) {
            float d0 = cd[u], d1 = cd[u + 1], d2 = cd[u + 2], d3 = cd[u + 3];
            ev = fmaf(d3, HI0f, fmaf(d2, HI2f, fmaf(d1, HI4f, fmaf(d0, HI6f, ev))));
            od = fmaf(d3, HI1f, fmaf(d2, HI3f, fmaf(d1, HI5f, fmaf(d0, HI7f, od))));
        }
        float2 o2;
        o2.x = FINAL ? fmaxf(ev, 0.0f) : ev;
        o2.y = FINAL ? fmaxf(od, 0.0f) : od;
        *reinterpret_cast<float2*>(out + 2 * u) = o2;
    }
}

// ---------------- kernel 1: per-row wavelet features (all in smem) ----------
extern "C" __global__ void __launch_bounds__(WTH)
wavelet_kernel(const float* __restrict__ x)
{
    __shared__ __align__(16) float s_cds[4138];
    __shared__ __align__(16) float bufX[4096];
    __shared__ __align__(16) float bufB[2052];

    int row = blockIdx.x;
    const float* xr = x + (size_t)row * 4096;
    float* hr = g_h + (size_t)row * 32768;

    for (int i = threadIdx.x; i < 4096; i += WTH) bufX[i] = xr[i];
    __syncthreads();

    // ---- analysis cascade: a_0 = x; (a_l, d_l) = dwt(a_{l-1}) ----
    {
        float* a_src = bufX;
        float* a_dst = bufB;
        #pragma unroll 1
        for (int l = 1; l <= 9; ++l) {
            dwt_stage(a_src, c_NA[l - 1], a_dst, s_cds + c_OFF[l - 1], c_NA[l]);
            __syncthreads();
            float* t = a_src; a_src = a_dst; a_dst = t;
        }
    }

    // ---- reconstructions for levels 2..9 ----
    // r = idwt(0, d_level); first inner step uses real d_{level-1}; rest zeros.
    // Trims are implicit: n at step j is always c_NA[j+1].
    #pragma unroll 1
    for (int level = 2; level <= 9; ++level) {
        float* ping = bufX;
        float* pong = bufB;
        idwt_stage<false, true, false>(nullptr, s_cds + c_OFF[level - 1],
                                       c_NA[level], ping);
        __syncthreads();
        if (level == 2) {
            // final step also carries real cd = cds[0]
            idwt_stage<true, true, true>(ping, s_cds + c_OFF[0], c_NA[1], hr);
        } else {
            idwt_stage<true, true, false>(ping, s_cds + c_OFF[level - 2],
                                          c_NA[level - 1], pong);
            __syncthreads();
            { float* t = ping; ping = pong; pong = t; }
            for (int j = level - 3; j >= 1; --j) {
                idwt_stage<true, false, false>(ping, nullptr, c_NA[j + 1], pong);
                __syncthreads();
                float* t = ping; ping = pong; pong = t;
            }
            idwt_stage<true, false, true>(ping, nullptr, c_NA[1],
                                          hr + (size_t)(level - 2) * 4096);
        }
        __syncthreads();
    }
}

// ---------------- kernel 2: split-K fp32 GEMM: part[s] = H_chunk * W0^T -----
#define BM 64
#define BN 64
#define BK 16
#define KCHUNK 8192

extern "C" __global__ void __launch_bounds__(256)
gemm_kernel(const float* __restrict__ W0)
{
    __shared__ __align__(16) float As[BK][BM + 4];
    __shared__ __align__(16) float Bs[BK][BN + 4];

    int m0 = blockIdx.x * BM;
    int n0 = blockIdx.y * BN;
    int sb = blockIdx.z;
    int tid = threadIdx.x;
    int tx = tid & 15;        // n direction
    int ty = tid >> 4;        // m direction
    int lr = tid >> 2;        // load row 0..63
    int lc = (tid & 3) * 4;   // load k-offset {0,4,8,12}

    const float* Aptr = g_h + (size_t)(m0 + lr) * 32768 + (size_t)sb * KCHUNK + lc;
    bool bvalid = (n0 + lr) < 181;
    const float* Bptr = W0 + (size_t)(bvalid ? (n0 + lr) : 0) * 32768
                        + (size_t)sb * KCHUNK + lc;

    float acc[4][4] = {};

    for (int kk = 0; kk < KCHUNK; kk += BK) {
        float4 av = *reinterpret_cast<const float4*>(Aptr); Aptr += BK;
        float4 bv = *reinterpret_cast<const float4*>(Bptr); Bptr += BK;
        if (!bvalid) bv = make_float4(0.f, 0.f, 0.f, 0.f);

        As[lc + 0][lr] = av.x; As[lc + 1][lr] = av.y;
        As[lc + 2][lr] = av.z; As[lc + 3][lr] = av.w;
        Bs[lc + 0][lr] = bv.x; Bs[lc + 1][lr] = bv.y;
        Bs[lc + 2][lr] = bv.z; Bs[lc + 3][lr] = bv.w;
        __syncthreads();

        #pragma unroll
        for (int p = 0; p < BK; ++p) {
            float4 af = *reinterpret_cast<const float4*>(&As[p][ty * 4]);
            float4 bf = *reinterpret_cast<const float4*>(&Bs[p][tx * 4]);
            float aa[4] = {af.x, af.y, af.z, af.w};
            float bb[4] = {bf.x, bf.y, bf.z, bf.w};
            #pragma unroll
            for (int i = 0; i < 4; ++i)
                #pragma unroll
                for (int j = 0; j < 4; ++j)
                    acc[i][j] = fmaf(aa[i], bb[j], acc[i][j]);
        }
        __syncthreads();
    }

    float* outp = g_part[sb];
    #pragma unroll
    for (int i = 0; i < 4; ++i) {
        int m = m0 + ty * 4 + i;
        #pragma unroll
        for (int j = 0; j < 4; ++j) {
            int nn = n0 + tx * 4 + j;
            if (nn < 181) outp[m * 181 + nn] = acc[i][j];
        }
    }
}

// ---------------- kernel 3: reduce partials + bias + relu + tiny MLP --------
extern "C" __global__ void __launch_bounds__(192)
mlp_kernel(const float* __restrict__ b0,
           const float* __restrict__ W1, const float* __restrict__ b1,
           const float* __restrict__ W2, const float* __restrict__ b2,
           float* __restrict__ out)
{
    __shared__ float sc[181];
    __shared__ float sh1[13];
    int row = blockIdx.x;
    int tid = threadIdx.x;

    if (tid < 181) {
        float v = b0[tid];
        #pragma unroll
        for (int s = 0; s < 4; ++s) v += g_part[s][row * 181 + tid];
        sc[tid] = fmaxf(v, 0.0f);
    }
    __syncthreads();

    if (tid < 13) {
        float v = b1[tid];
        const float* w = W1 + tid * 181;
        #pragma unroll 4
        for (int j = 0; j < 181; ++j) v = fmaf(sc[j], w[j], v);
        sh1[tid] = fmaxf(v, 0.0f);
    }
    __syncthreads();

    if (tid < 10) {
        float v = b2[tid];
        const float* w = W2 + tid * 13;
        #pragma unroll
        for (int i = 0; i < 13; ++i) v = fmaf(sh1[i], w[i], v);
        out[row * 10 + tid] = v;
    }
}

// ---------------- launcher ---------------------------------------------------
extern "C" void kernel_launch(void* const* d_in, const int* in_sizes, int n_in,
                              void* d_out, int out_size)
{
    const float* x1 = (const float*)d_in[0];
    // d_in[1] = x2, d_in[2] = x3 (unused by reference)
    const float* W0 = (const float*)d_in[3];
    const float* b0 = (const float*)d_in[4];
    const float* W1 = (const float*)d_in[5];
    const float* b1 = (const float*)d_in[6];
    const float* W2 = (const float*)d_in[7];
    const float* b2 = (const float*)d_in[8];
    float* out = (float*)d_out;

    wavelet_kernel<<<2048, WTH>>>(x1);

    dim3 g(2048 / BM, (181 + BN - 1) / BN, 4);   // 32 x 3 x 4 = 384 CTAs
    gemm_kernel<<<g, 256>>>(W0);

    mlp_kernel<<<2048, 192>>>(b0, W1, b1, W2, b2, out);
}

// round 9
// speedup vs baseline: 2.6850x; 2.6850x over previous
#include <cuda_runtime.h>
#include <cuda_bf16.h>
#include <cstdint>

#define WTH 256

// ---------------- filter constants (db4-style reconstruction filters) -------
#define LO0f ( 0.23037781330885523f)
#define LO1f ( 0.7148465705525415f)
#define LO2f ( 0.6308807679295904f)
#define LO3f (-0.02798376941698385f)
#define LO4f (-0.18703481171888114f)
#define LO5f ( 0.030841381835986965f)
#define LO6f ( 0.032883011666982945f)
#define LO7f (-0.010597401784997278f)
#define HI0f (-0.010597401784997278f)
#define HI1f (-0.032883011666982945f)
#define HI2f ( 0.030841381835986965f)
#define HI3f ( 0.18703481171888114f)
#define HI4f (-0.02798376941698385f)
#define HI5f (-0.6308807679295904f)
#define HI6f ( 0.7148465705525415f)
#define HI7f (-0.23037781330885523f)

__constant__ int c_NA[10]  = {4096, 2051, 1029, 518, 262, 134, 70, 38, 22, 14};
__constant__ int c_OFF[9]  = {0, 2051, 3080, 3598, 3860, 3994, 4064, 4102, 4124};

// ---------------- scratch (device globals; no runtime allocation) -----------
#define NSPLIT 9
__device__ __align__(128) __nv_bfloat16 g_Ah[2048UL * 32768UL];
__device__ __align__(128) __nv_bfloat16 g_Al[2048UL * 32768UL];
__device__ __align__(128) __nv_bfloat16 g_Wh[192UL * 32768UL];
__device__ __align__(128) __nv_bfloat16 g_Wl[192UL * 32768UL];
__device__ __align__(128) float g_part[NSPLIT][2048 * 192];

// ============================ PTX helpers ====================================
__device__ __forceinline__ uint32_t smem_u32(const void* p) {
    uint32_t a;
    asm("{ .reg .u64 t; cvta.to.shared.u64 t, %1; cvt.u32.u64 %0, t; }"
        : "=r"(a) : "l"(p));
    return a;
}
__device__ __forceinline__ void cp16(uint32_t dst, const void* src) {
    asm volatile("cp.async.cg.shared.global [%0], [%1], 16;"
                 :: "r"(dst), "l"(src) : "memory");
}
__device__ __forceinline__ void cp_commit() {
    asm volatile("cp.async.commit_group;" ::: "memory");
}
template <int N>
__device__ __forceinline__ void cp_wait() {
    asm volatile("cp.async.wait_group %0;" :: "n"(N) : "memory");
}
__device__ __forceinline__ void ldm4(uint32_t* r, uint32_t a) {
    asm volatile("ldmatrix.sync.aligned.m8n8.x4.shared.b16 {%0,%1,%2,%3}, [%4];"
                 : "=r"(r[0]), "=r"(r[1]), "=r"(r[2]), "=r"(r[3]) : "r"(a));
}
__device__ __forceinline__ void mma_bf16(float* c, const uint32_t* a,
                                         const uint32_t* b) {
    asm volatile("mma.sync.aligned.m16n8k16.row.col.f32.bf16.bf16.f32 "
                 "{%0,%1,%2,%3}, {%4,%5,%6,%7}, {%8,%9}, {%0,%1,%2,%3};"
                 : "+f"(c[0]), "+f"(c[1]), "+f"(c[2]), "+f"(c[3])
                 : "r"(a[0]), "r"(a[1]), "r"(a[2]), "r"(a[3]),
                   "r"(b[0]), "r"(b[1]));
}

// ================= bf16 hi/lo split helper ==================================
__device__ __forceinline__ void bf_split(float v, __nv_bfloat16& h, __nv_bfloat16& l) {
    h = __float2bfloat16_rn(v);
    l = __float2bfloat16_rn(v - __bfloat162float(h));
}

// ---------------- DWT stage: src[n] -> ca[m], cd[m] -------------------------
__device__ __forceinline__ void dwt_stage(const float* __restrict__ src, int n,
                                          float* __restrict__ ca,
                                          float* __restrict__ cd, int m)
{
    const float LO[8] = {LO0f, LO1f, LO2f, LO3f, LO4f, LO5f, LO6f, LO7f};
    const float HI[8] = {HI0f, HI1f, HI2f, HI3f, HI4f, HI5f, HI6f, HI7f};
    for (int k = threadIdx.x; k < m; k += WTH) {
        int base = 2 * k;
        float alo = 0.0f, ahi = 0.0f;
        if (base >= 6 && base <= n - 2) {
            const float* p = src + base - 6;
            #pragma unroll
            for (int t = 0; t < 8; ++t) {
                float v = p[t];
                alo = fmaf(v, LO[t], alo);
                ahi = fmaf(v, HI[t], ahi);
            }
        } else {
            #pragma unroll
            for (int t = 0; t < 8; ++t) {
                int idx = base + t;
                int e = (idx < 6) ? (5 - idx)
                                  : ((idx < n + 6) ? (idx - 6) : (2 * n + 5 - idx));
                float v = src[e];
                alo = fmaf(v, LO[t], alo);
                ahi = fmaf(v, HI[t], ahi);
            }
        }
        ca[k] = alo;
        cd[k] = ahi;
    }
}

// ---------------- IDWT stage (intermediate, fp32 smem out) ------------------
template <bool HAS_CA, bool HAS_CD>
__device__ __forceinline__ void idwt_stage(const float* __restrict__ ca,
                                           const float* __restrict__ cd,
                                           int n, float* __restrict__ out)
{
    int half = n - 3;
    for (int u = threadIdx.x; u < half; u += WTH) {
        float ev = 0.0f, od = 0.0f;
        if (HAS_CA) {
            float a0 = ca[u], a1 = ca[u + 1], a2 = ca[u + 2], a3 = ca[u + 3];
            ev = fmaf(a3, LO0f, fmaf(a2, LO2f, fmaf(a1, LO4f, a0 * LO6f)));
            od = fmaf(a3, LO1f, fmaf(a2, LO3f, fmaf(a1, LO5f, a0 * LO7f)));
        }
        if (HAS_CD) {
            float d0 = cd[u], d1 = cd[u + 1], d2 = cd[u + 2], d3 = cd[u + 3];
            ev = fmaf(d3, HI0f, fmaf(d2, HI2f, fmaf(d1, HI4f, fmaf(d0, HI6f, ev))));
            od = fmaf(d3, HI1f, fmaf(d2, HI3f, fmaf(d1, HI5f, fmaf(d0, HI7f, od))));
        }
        float2 o2; o2.x = ev; o2.y = od;
        *reinterpret_cast<float2*>(out + 2 * u) = o2;
    }
}

// ---------------- IDWT final: relu + bf16 hi/lo split to gmem ---------------
template <bool HAS_CD>
__device__ __forceinline__ void idwt_final(const float* __restrict__ ca,
                                           const float* __restrict__ cd, int n,
                                           __nv_bfloat16* __restrict__ hi,
                                           __nv_bfloat16* __restrict__ lo)
{
    int half = n - 3;
    for (int u = threadIdx.x; u < half; u += WTH) {
        float a0 = ca[u], a1 = ca[u + 1], a2 = ca[u + 2], a3 = ca[u + 3];
        float ev = fmaf(a3, LO0f, fmaf(a2, LO2f, fmaf(a1, LO4f, a0 * LO6f)));
        float od = fmaf(a3, LO1f, fmaf(a2, LO3f, fmaf(a1, LO5f, a0 * LO7f)));
        if (HAS_CD) {
            float d0 = cd[u], d1 = cd[u + 1], d2 = cd[u + 2], d3 = cd[u + 3];
            ev = fmaf(d3, HI0f, fmaf(d2, HI2f, fmaf(d1, HI4f, fmaf(d0, HI6f, ev))));
            od = fmaf(d3, HI1f, fmaf(d2, HI3f, fmaf(d1, HI5f, fmaf(d0, HI7f, od))));
        }
        ev = fmaxf(ev, 0.0f);
        od = fmaxf(od, 0.0f);
        __nv_bfloat162 hv, lv;
        bf_split(ev, hv.x, lv.x);
        bf_split(od, hv.y, lv.y);
        *reinterpret_cast<__nv_bfloat162*>(hi + 2 * u) = hv;
        *reinterpret_cast<__nv_bfloat162*>(lo + 2 * u) = lv;
    }
}

// ---------------- kernel 1: per-row wavelet features (all in smem) ----------
extern "C" __global__ void __launch_bounds__(WTH)
wavelet_kernel(const float* __restrict__ x)
{
    __shared__ __align__(16) float s_cds[4138];
    __shared__ __align__(16) float bufX[4096];
    __shared__ __align__(16) float bufB[2052];

    int row = blockIdx.x;
    const float* xr = x + (size_t)row * 4096;
    __nv_bfloat16* hh = g_Ah + (size_t)row * 32768;
    __nv_bfloat16* hl = g_Al + (size_t)row * 32768;

    for (int i = threadIdx.x; i < 4096; i += WTH) bufX[i] = xr[i];
    __syncthreads();

    {
        float* a_src = bufX;
        float* a_dst = bufB;
        #pragma unroll 1
        for (int l = 1; l <= 9; ++l) {
            dwt_stage(a_src, c_NA[l - 1], a_dst, s_cds + c_OFF[l - 1], c_NA[l]);
            __syncthreads();
            float* t = a_src; a_src = a_dst; a_dst = t;
        }
    }

    #pragma unroll 1
    for (int level = 2; level <= 9; ++level) {
        float* ping = bufX;
        float* pong = bufB;
        idwt_stage<false, true>(nullptr, s_cds + c_OFF[level - 1], c_NA[level], ping);
        __syncthreads();
        if (level == 2) {
            idwt_final<true>(ping, s_cds + c_OFF[0], c_NA[1], hh, hl);
        } else {
            idwt_stage<true, true>(ping, s_cds + c_OFF[level - 2], c_NA[level - 1], pong);
            __syncthreads();
            { float* t = ping; ping = pong; pong = t; }
            for (int j = level - 3; j >= 1; --j) {
                idwt_stage<true, false>(ping, nullptr, c_NA[j + 1], pong);
                __syncthreads();
                float* t = ping; ping = pong; pong = t;
            }
            idwt_final<false>(ping, nullptr, c_NA[1],
                              hh + (size_t)(level - 2) * 4096,
                              hl + (size_t)(level - 2) * 4096);
        }
        __syncthreads();
    }
}

// ---------------- kernel 1b: split W0 into bf16 hi/lo (padded to 192 rows) --
extern "C" __global__ void __launch_bounds__(256)
wconv_kernel(const float* __restrict__ W0)
{
    int i = blockIdx.x * 256 + threadIdx.x;   // over 192*32768 elements
    int row = i >> 15;
    int col = i & 32767;
    float v = (row < 181) ? W0[(size_t)row * 32768 + col] : 0.0f;
    __nv_bfloat16 h, l;
    bf_split(v, h, l);
    g_Wh[i] = h;
    g_Wl[i] = l;
}

// ---------------- kernel 2: HMMA (mma.sync) bf16x3 split-K GEMM -------------
// CTA tile: 128(M) x 192(N) full-N; BK = 32 bf16; 3-stage cp.async pipeline.
// smem per stage: Ah(10240) Al(10240) Bh(15360) Bl(15360) = 51200 B
// padded row stride: 40 bf16 = 80 B (conflict-free ldmatrix)
#define STAGE_B   51200
#define GEMM_SMEM (3 * STAGE_B)
#define KSTEPS_TOT 1024          // 32768 / 32
#define SB_STEPS   114           // ceil(1024/9)

__device__ __forceinline__ void stage_load(uint32_t sbase, int m0, int kstep, int tid)
{
    size_t kb = (size_t)kstep * 64;           // byte offset along k
    #pragma unroll
    for (int j = 0; j < 10; ++j) {
        int c = tid + j * 256;
        uint32_t dst;
        const char* src;
        if (c < 1024) {                        // A tiles (hi then lo)
            int mat = c >> 9, rc = c & 511, row = rc >> 2, kc = rc & 3;
            dst = sbase + mat * 10240 + row * 80 + kc * 16;
            const char* base = mat ? (const char*)g_Al : (const char*)g_Ah;
            src = base + ((size_t)(m0 + row) << 16) + kb + kc * 16;
        } else {                               // W tiles (hi then lo)
            int c2 = c - 1024;
            int mat = (c2 >= 768);
            int rc = c2 - (mat ? 768 : 0);
            int row = rc >> 2, kc = rc & 3;
            dst = sbase + 20480 + mat * 15360 + row * 80 + kc * 16;
            const char* base = mat ? (const char*)g_Wl : (const char*)g_Wh;
            src = base + ((size_t)row << 16) + kb + kc * 16;
        }
        cp16(dst, src);
    }
    cp_commit();
}

extern "C" __global__ void __launch_bounds__(256, 1)
gemm_hmma_kernel()
{
    extern __shared__ __align__(128) char smem[];
    uint32_t sbase = smem_u32(smem);
    int tid = threadIdx.x;
    int wid = tid >> 5;
    int l   = tid & 31;
    int wm  = wid >> 2;     // 0..1 : 64 rows each
    int wn  = wid & 3;      // 0..3 : 48 cols each
    int m0  = blockIdx.x * 128;
    int sb  = blockIdx.y;
    int start = sb * SB_STEPS;
    int nst = KSTEPS_TOT - start;
    if (nst > SB_STEPS) nst = SB_STEPS;

    float acc[4][6][4] = {};

    stage_load(sbase,            m0, start,     tid);
    stage_load(sbase + STAGE_B,  m0, start + 1, tid);

    // per-thread ldmatrix base offsets
    uint32_t aoff = (uint32_t)((wm * 64 + (l & 15)) * 80 + (l >> 4) * 16);
    uint32_t boff = (uint32_t)(20480 +
                    (wn * 48 + (l & 7) + ((l >> 4) & 1) * 8) * 80 +
                    ((l >> 3) & 1) * 16);

    int st = 0;
    #pragma unroll 1
    for (int it = 0; it < nst; ++it) {
        if (it == nst - 1) cp_wait<0>(); else cp_wait<1>();
        __syncthreads();
        uint32_t buf = sbase + (uint32_t)st * STAGE_B;
        if (it + 2 < nst) {
            int st2 = st + 2; if (st2 >= 3) st2 -= 3;
            stage_load(sbase + (uint32_t)st2 * STAGE_B, m0, start + it + 2, tid);
        }

        #pragma unroll
        for (int ks = 0; ks < 2; ++ks) {
            uint32_t Ah[4][4], Al[4][4], Bh[3][4], Bl[3][4];
            #pragma unroll
            for (int mi = 0; mi < 4; ++mi) {
                uint32_t a = buf + aoff + mi * (16 * 80) + ks * 32;
                ldm4(Ah[mi], a);
                ldm4(Al[mi], a + 10240);
            }
            #pragma unroll
            for (int nj = 0; nj < 3; ++nj) {
                uint32_t b = buf + boff + nj * (16 * 80) + ks * 32;
                ldm4(Bh[nj], b);
                ldm4(Bl[nj], b + 15360);
            }
            // product-major ordering keeps C RAW chains 24 mmas apart
            #pragma unroll
            for (int p = 0; p < 3; ++p)
                #pragma unroll
                for (int mi = 0; mi < 4; ++mi)
                    #pragma unroll
                    for (int nj = 0; nj < 3; ++nj)
                        #pragma unroll
                        for (int h = 0; h < 2; ++h) {
                            const uint32_t* A = (p == 1) ? Al[mi] : Ah[mi];
                            const uint32_t* B = (p == 2) ? &Bl[nj][h * 2]
                                                         : &Bh[nj][h * 2];
                            mma_bf16(acc[mi][nj * 2 + h], A, B);
                        }
        }
        ++st; if (st == 3) st = 0;
    }

    // epilogue: direct partial store
    float* outp = g_part[sb];
    #pragma unroll
    for (int mi = 0; mi < 4; ++mi) {
        int r0 = m0 + wm * 64 + mi * 16 + (l >> 2);
        #pragma unroll
        for (int n = 0; n < 6; ++n) {
            int col = wn * 48 + n * 8 + (l & 3) * 2;
            float2 v0, v1;
            v0.x = acc[mi][n][0]; v0.y = acc[mi][n][1];
            v1.x = acc[mi][n][2]; v1.y = acc[mi][n][3];
            *reinterpret_cast<float2*>(outp + (size_t)r0 * 192 + col) = v0;
            *reinterpret_cast<float2*>(outp + (size_t)(r0 + 8) * 192 + col) = v1;
        }
    }
}

// ---------------- kernel 3: reduce partials + bias + relu + tiny MLP --------
extern "C" __global__ void __launch_bounds__(192)
mlp_kernel(const float* __restrict__ b0,
           const float* __restrict__ W1, const float* __restrict__ b1,
           const float* __restrict__ W2, const float* __restrict__ b2,
           float* __restrict__ out)
{
    __shared__ float sc[181];
    __shared__ float sh1[13];
    int row = blockIdx.x;
    int tid = threadIdx.x;

    if (tid < 181) {
        float v = b0[tid];
        #pragma unroll
        for (int s = 0; s < NSPLIT; ++s) v += g_part[s][(size_t)row * 192 + tid];
        sc[tid] = fmaxf(v, 0.0f);
    }
    __syncthreads();

    if (tid < 13) {
        float v = b1[tid];
        const float* w = W1 + tid * 181;
        #pragma unroll 4
        for (int j = 0; j < 181; ++j) v = fmaf(sc[j], w[j], v);
        sh1[tid] = fmaxf(v, 0.0f);
    }
    __syncthreads();

    if (tid < 10) {
        float v = b2[tid];
        const float* w = W2 + tid * 13;
        #pragma unroll
        for (int i = 0; i < 13; ++i) v = fmaf(sh1[i], w[i], v);
        out[row * 10 + tid] = v;
    }
}

// ---------------- launcher ---------------------------------------------------
extern "C" void kernel_launch(void* const* d_in, const int* in_sizes, int n_in,
                              void* d_out, int out_size)
{
    const float* x1 = (const float*)d_in[0];
    const float* W0 = (const float*)d_in[3];
    const float* b0 = (const float*)d_in[4];
    const float* W1 = (const float*)d_in[5];
    const float* b1 = (const float*)d_in[6];
    const float* W2 = (const float*)d_in[7];
    const float* b2 = (const float*)d_in[8];
    float* out = (float*)d_out;

    wavelet_kernel<<<2048, WTH>>>(x1);
    wconv_kernel<<<192 * 32768 / 256, 256>>>(W0);

    static int smem_set = 0;
    if (!smem_set) {
        cudaFuncSetAttribute(gemm_hmma_kernel,
                             cudaFuncAttributeMaxDynamicSharedMemorySize,
                             GEMM_SMEM);
        smem_set = 1;
    }
    dim3 gg(2048 / 128, NSPLIT);   // 16 x 9 = 144 CTAs (one wave)
    gemm_hmma_kernel<<<gg, 256, GEMM_SMEM>>>();

    mlp_kernel<<<2048, 192>>>(b0, W1, b1, W2, b2, out);
}

// round 11
// speedup vs baseline: 4.3344x; 1.6143x over previous
#include <cuda_runtime.h>
#include <cuda_fp16.h>
#include <cstdint>

#define WTH 256

// ---------------- filter constants (db4-style reconstruction filters) -------
#define LO0f ( 0.23037781330885523f)
#define LO1f ( 0.7148465705525415f)
#define LO2f ( 0.6308807679295904f)
#define LO3f (-0.02798376941698385f)
#define LO4f (-0.18703481171888114f)
#define LO5f ( 0.030841381835986965f)
#define LO6f ( 0.032883011666982945f)
#define LO7f (-0.010597401784997278f)
#define HI0f (-0.010597401784997278f)
#define HI1f (-0.032883011666982945f)
#define HI2f ( 0.030841381835986965f)
#define HI3f ( 0.18703481171888114f)
#define HI4f (-0.02798376941698385f)
#define HI5f (-0.6308807679295904f)
#define HI6f ( 0.7148465705525415f)
#define HI7f (-0.23037781330885523f)

__constant__ int c_NA[10]  = {4096, 2051, 1029, 518, 262, 134, 70, 38, 22, 14};
__constant__ int c_OFF[9]  = {0, 2051, 3080, 3598, 3860, 3994, 4064, 4102, 4124};

// ---------------- scratch (device globals; no runtime allocation) -----------
#define NSPLIT 9
__device__ __align__(128) __half g_A[2048UL * 32768UL];    // relu(feats), fp16
__device__ __align__(128) __half g_W[192UL * 32768UL];     // W0 padded, fp16
__device__ __align__(128) float  g_part[NSPLIT][2048 * 192];
__device__ __align__(128) float  g_h0[2048 * 192];         // reduced+relu'd L0

// ============================ PTX helpers ====================================
__device__ __forceinline__ uint32_t smem_u32(const void* p) {
    uint32_t a;
    asm("{ .reg .u64 t; cvta.to.shared.u64 t, %1; cvt.u32.u64 %0, t; }"
        : "=r"(a) : "l"(p));
    return a;
}
__device__ __forceinline__ void cp16(uint32_t dst, const void* src) {
    asm volatile("cp.async.cg.shared.global [%0], [%1], 16;"
                 :: "r"(dst), "l"(src) : "memory");
}
__device__ __forceinline__ void cp_commit() {
    asm volatile("cp.async.commit_group;" ::: "memory");
}
template <int N>
__device__ __forceinline__ void cp_wait() {
    asm volatile("cp.async.wait_group %0;" :: "n"(N) : "memory");
}
__device__ __forceinline__ void ldm4(uint32_t* r, uint32_t a) {
    asm volatile("ldmatrix.sync.aligned.m8n8.x4.shared.b16 {%0,%1,%2,%3}, [%4];"
                 : "=r"(r[0]), "=r"(r[1]), "=r"(r[2]), "=r"(r[3]) : "r"(a));
}
__device__ __forceinline__ void mma_f16(float* c, const uint32_t* a,
                                        const uint32_t* b) {
    asm volatile("mma.sync.aligned.m16n8k16.row.col.f32.f16.f16.f32 "
                 "{%0,%1,%2,%3}, {%4,%5,%6,%7}, {%8,%9}, {%0,%1,%2,%3};"
                 : "+f"(c[0]), "+f"(c[1]), "+f"(c[2]), "+f"(c[3])
                 : "r"(a[0]), "r"(a[1]), "r"(a[2]), "r"(a[3]),
                   "r"(b[0]), "r"(b[1]));
}

// ---------------- DWT stage: src[n] -> ca[m], cd[m] -------------------------
__device__ __forceinline__ void dwt_stage(const float* __restrict__ src, int n,
                                          float* __restrict__ ca,
                                          float* __restrict__ cd, int m)
{
    const float LO[8] = {LO0f, LO1f, LO2f, LO3f, LO4f, LO5f, LO6f, LO7f};
    const float HI[8] = {HI0f, HI1f, HI2f, HI3f, HI4f, HI5f, HI6f, HI7f};
    for (int k = threadIdx.x; k < m; k += WTH) {
        int base = 2 * k;
        float alo = 0.0f, ahi = 0.0f;
        if (base >= 6 && base <= n - 2) {
            const float* p = src + base - 6;
            #pragma unroll
            for (int t = 0; t < 8; ++t) {
                float v = p[t];
                alo = fmaf(v, LO[t], alo);
                ahi = fmaf(v, HI[t], ahi);
            }
        } else {
            #pragma unroll
            for (int t = 0; t < 8; ++t) {
                int idx = base + t;
                int e = (idx < 6) ? (5 - idx)
                                  : ((idx < n + 6) ? (idx - 6) : (2 * n + 5 - idx));
                float v = src[e];
                alo = fmaf(v, LO[t], alo);
                ahi = fmaf(v, HI[t], ahi);
            }
        }
        ca[k] = alo;
        cd[k] = ahi;
    }
}

// ---------------- IDWT stage (intermediate, fp32 smem out) ------------------
template <bool HAS_CA, bool HAS_CD>
__device__ __forceinline__ void idwt_stage(const float* __restrict__ ca,
                                           const float* __restrict__ cd,
                                           int n, float* __restrict__ out)
{
    int half = n - 3;
    for (int u = threadIdx.x; u < half; u += WTH) {
        float ev = 0.0f, od = 0.0f;
        if (HAS_CA) {
            float a0 = ca[u], a1 = ca[u + 1], a2 = ca[u + 2], a3 = ca[u + 3];
            ev = fmaf(a3, LO0f, fmaf(a2, LO2f, fmaf(a1, LO4f, a0 * LO6f)));
            od = fmaf(a3, LO1f, fmaf(a2, LO3f, fmaf(a1, LO5f, a0 * LO7f)));
        }
        if (HAS_CD) {
            float d0 = cd[u], d1 = cd[u + 1], d2 = cd[u + 2], d3 = cd[u + 3];
            ev = fmaf(d3, HI0f, fmaf(d2, HI2f, fmaf(d1, HI4f, fmaf(d0, HI6f, ev))));
            od = fmaf(d3, HI1f, fmaf(d2, HI3f, fmaf(d1, HI5f, fmaf(d0, HI7f, od))));
        }
        float2 o2; o2.x = ev; o2.y = od;
        *reinterpret_cast<float2*>(out + 2 * u) = o2;
    }
}

// ---------------- IDWT final: relu + fp16 store to gmem ---------------------
template <bool HAS_CD>
__device__ __forceinline__ void idwt_final(const float* __restrict__ ca,
                                           const float* __restrict__ cd, int n,
                                           __half* __restrict__ dst)
{
    int half = n - 3;
    for (int u = threadIdx.x; u < half; u += WTH) {
        float a0 = ca[u], a1 = ca[u + 1], a2 = ca[u + 2], a3 = ca[u + 3];
        float ev = fmaf(a3, LO0f, fmaf(a2, LO2f, fmaf(a1, LO4f, a0 * LO6f)));
        float od = fmaf(a3, LO1f, fmaf(a2, LO3f, fmaf(a1, LO5f, a0 * LO7f)));
        if (HAS_CD) {
            float d0 = cd[u], d1 = cd[u + 1], d2 = cd[u + 2], d3 = cd[u + 3];
            ev = fmaf(d3, HI0f, fmaf(d2, HI2f, fmaf(d1, HI4f, fmaf(d0, HI6f, ev))));
            od = fmaf(d3, HI1f, fmaf(d2, HI3f, fmaf(d1, HI5f, fmaf(d0, HI7f, od))));
        }
        ev = fmaxf(ev, 0.0f);
        od = fmaxf(od, 0.0f);
        *reinterpret_cast<__half2*>(dst + 2 * u) = __floats2half2_rn(ev, od);
    }
}

// ---------------- kernel 1: per-row wavelet features (all in smem) ----------
extern "C" __global__ void __launch_bounds__(WTH)
wavelet_kernel(const float* __restrict__ x)
{
    __shared__ __align__(16) float s_cds[4138];
    __shared__ __align__(16) float bufX[4096];
    __shared__ __align__(16) float bufB[2052];

    int row = blockIdx.x;
    const float* xr = x + (size_t)row * 4096;
    __half* hr = g_A + (size_t)row * 32768;

    for (int i = threadIdx.x; i < 4096; i += WTH) bufX[i] = xr[i];
    __syncthreads();

    {
        float* a_src = bufX;
        float* a_dst = bufB;
        #pragma unroll 1
        for (int l = 1; l <= 9; ++l) {
            dwt_stage(a_src, c_NA[l - 1], a_dst, s_cds + c_OFF[l - 1], c_NA[l]);
            __syncthreads();
            float* t = a_src; a_src = a_dst; a_dst = t;
        }
    }

    #pragma unroll 1
    for (int level = 2; level <= 9; ++level) {
        float* ping = bufX;
        float* pong = bufB;
        idwt_stage<false, true>(nullptr, s_cds + c_OFF[level - 1], c_NA[level], ping);
        __syncthreads();
        if (level == 2) {
            idwt_final<true>(ping, s_cds + c_OFF[0], c_NA[1], hr);
        } else {
            idwt_stage<true, true>(ping, s_cds + c_OFF[level - 2], c_NA[level - 1], pong);
            __syncthreads();
            { float* t = ping; ping = pong; pong = t; }
            for (int j = level - 3; j >= 1; --j) {
                idwt_stage<true, false>(ping, nullptr, c_NA[j + 1], pong);
                __syncthreads();
                float* t = ping; ping = pong; pong = t;
            }
            idwt_final<false>(ping, nullptr, c_NA[1],
                              hr + (size_t)(level - 2) * 4096);
        }
        __syncthreads();
    }
}

// ---------------- kernel 1b: W0 -> fp16 (padded to 192 rows) ----------------
extern "C" __global__ void __launch_bounds__(256)
wconv_kernel(const float* __restrict__ W0)
{
    int i = blockIdx.x * 256 + threadIdx.x;   // over 192*32768 elements
    int row = i >> 15;
    int col = i & 32767;
    float v = (row < 181) ? W0[(size_t)row * 32768 + col] : 0.0f;
    g_W[i] = __float2half_rn(v);
}

// ---------------- kernel 2: HMMA fp16 single-product split-K GEMM -----------
// CTA tile: 128(M) x 192(N) full-N; BK = 32 halves; 4-stage cp.async pipeline.
// smem per stage: A(128x80B=10240) + W(192x80B=15360) = 25600 B
// padded row stride: 40 halves = 80 B (conflict-free ldmatrix)
#define STAGE_B   25600
#define NSTAGE    4
#define GEMM_SMEM (NSTAGE * STAGE_B)
#define KSTEPS_TOT 1024          // 32768 / 32
#define SB_STEPS   114           // ceil(1024/9)

__device__ __forceinline__ void stage_load(uint32_t sbase, int m0, int kstep, int tid)
{
    size_t kb = (size_t)kstep * 64;           // byte offset along k
    #pragma unroll
    for (int j = 0; j < 5; ++j) {             // 1280 16B chunks / 256 threads
        int c = tid + j * 256;
        uint32_t dst;
        const char* src;
        if (c < 512) {                         // A tile: 128 rows x 4 chunks
            int row = c >> 2, kc = c & 3;
            dst = sbase + row * 80 + kc * 16;
            src = (const char*)g_A + ((size_t)(m0 + row) << 16) + kb + kc * 16;
        } else {                               // W tile: 192 rows x 4 chunks
            int rc = c - 512;
            int row = rc >> 2, kc = rc & 3;
            dst = sbase + 10240 + row * 80 + kc * 16;
            src = (const char*)g_W + ((size_t)row << 16) + kb + kc * 16;
        }
        cp16(dst, src);
    }
    cp_commit();
}

extern "C" __global__ void __launch_bounds__(256, 1)
gemm_hmma_kernel()
{
    extern __shared__ __align__(128) char smem[];
    uint32_t sbase = smem_u32(smem);
    int tid = threadIdx.x;
    int wid = tid >> 5;
    int l   = tid & 31;
    int wm  = wid >> 2;     // 0..1 : 64 rows each
    int wn  = wid & 3;      // 0..3 : 48 cols each
    int m0  = blockIdx.x * 128;
    int sb  = blockIdx.y;
    int start = sb * SB_STEPS;
    int nst = KSTEPS_TOT - start;
    if (nst > SB_STEPS) nst = SB_STEPS;

    float acc[4][6][4] = {};

    stage_load(sbase,               m0, start,     tid);
    stage_load(sbase + STAGE_B,     m0, start + 1, tid);
    stage_load(sbase + 2 * STAGE_B, m0, start + 2, tid);

    uint32_t aoff = (uint32_t)((wm * 64 + (l & 15)) * 80 + (l >> 4) * 16);
    uint32_t boff = (uint32_t)(10240 +
                    (wn * 48 + (l & 7) + ((l >> 4) & 1) * 8) * 80 +
                    ((l >> 3) & 1) * 16);

    #pragma unroll 1
    for (int it = 0; it < nst; ++it) {
        if (it >= nst - 3) cp_wait<0>(); else cp_wait<2>();
        __syncthreads();
        uint32_t buf = sbase + (uint32_t)(it & 3) * STAGE_B;
        if (it + 3 < nst)
            stage_load(sbase + (uint32_t)((it + 3) & 3) * STAGE_B,
                       m0, start + it + 3, tid);

        #pragma unroll
        for (int ks = 0; ks < 2; ++ks) {
            uint32_t A[4][4], B[3][4];
            #pragma unroll
            for (int mi = 0; mi < 4; ++mi)
                ldm4(A[mi], buf + aoff + mi * (16 * 80) + ks * 32);
            #pragma unroll
            for (int nj = 0; nj < 3; ++nj)
                ldm4(B[nj], buf + boff + nj * (16 * 80) + ks * 32);
            #pragma unroll
            for (int mi = 0; mi < 4; ++mi)
                #pragma unroll
                for (int nj = 0; nj < 3; ++nj)
                    #pragma unroll
                    for (int h = 0; h < 2; ++h)
                        mma_f16(acc[mi][nj * 2 + h], A[mi], &B[nj][h * 2]);
        }
    }

    // epilogue: direct partial store
    float* outp = g_part[sb];
    #pragma unroll
    for (int mi = 0; mi < 4; ++mi) {
        int r0 = m0 + wm * 64 + mi * 16 + (l >> 2);
        #pragma unroll
        for (int n = 0; n < 6; ++n) {
            int col = wn * 48 + n * 8 + (l & 3) * 2;
            float2 v0, v1;
            v0.x = acc[mi][n][0]; v0.y = acc[mi][n][1];
            v1.x = acc[mi][n][2]; v1.y = acc[mi][n][3];
            *reinterpret_cast<float2*>(outp + (size_t)r0 * 192 + col) = v0;
            *reinterpret_cast<float2*>(outp + (size_t)(r0 + 8) * 192 + col) = v1;
        }
    }
}

// ---------------- kernel 3a: reduce partials + bias + relu ------------------
extern "C" __global__ void __launch_bounds__(256)
reduce_kernel(const float* __restrict__ b0)
{
    int i = blockIdx.x * 256 + threadIdx.x;   // over 2048*192
    int col = i % 192;
    float v = (col < 181) ? b0[col] : 0.0f;
    #pragma unroll
    for (int s = 0; s < NSPLIT; ++s) v += g_part[s][i];
    g_h0[i] = fmaxf(v, 0.0f);
}

// ---------------- kernel 3b: tiny MLP, 16 rows per block --------------------
#define MROWS 16
extern "C" __global__ void __launch_bounds__(256)
mlp_kernel(const float* __restrict__ W1, const float* __restrict__ b1,
           const float* __restrict__ W2, const float* __restrict__ b2,
           float* __restrict__ out)
{
    __shared__ float sW1[13 * 181];
    __shared__ float sW2[10 * 13];
    __shared__ float sb1[13], sb2[10];
    __shared__ float sc[MROWS][184];
    __shared__ float sh[MROWS][16];

    int tid = threadIdx.x;
    int row0 = blockIdx.x * MROWS;

    for (int i = tid; i < 13 * 181; i += 256) sW1[i] = W1[i];
    if (tid < 130) sW2[tid] = W2[tid];
    if (tid < 13) sb1[tid] = b1[tid];
    if (tid < 10) sb2[tid] = b2[tid];

    for (int i = tid; i < MROWS * 192; i += 256) {
        int r = i / 192, c = i % 192;
        float v = g_h0[(size_t)(row0 + r) * 192 + c];
        if (c < 181) sc[r][c] = v;
    }
    __syncthreads();

    if (tid < MROWS * 13) {
        int r = tid / 13, o = tid % 13;
        float v = sb1[o];
        const float* w = sW1 + o * 181;
        #pragma unroll 4
        for (int j = 0; j < 181; ++j) v = fmaf(sc[r][j], w[j], v);
        sh[r][o] = fmaxf(v, 0.0f);
    }
    __syncthreads();

    if (tid < MROWS * 10) {
        int r = tid / 10, o = tid % 10;
        float v = sb2[o];
        #pragma unroll
        for (int i = 0; i < 13; ++i) v = fmaf(sh[r][i], sW2[o * 13 + i], v);
        out[(size_t)(row0 + r) * 10 + o] = v;
    }
}

// ---------------- launcher ---------------------------------------------------
extern "C" void kernel_launch(void* const* d_in, const int* in_sizes, int n_in,
                              void* d_out, int out_size)
{
    const float* x1 = (const float*)d_in[0];
    const float* W0 = (const float*)d_in[3];
    const float* b0 = (const float*)d_in[4];
    const float* W1 = (const float*)d_in[5];
    const float* b1 = (const float*)d_in[6];
    const float* W2 = (const float*)d_in[7];
    const float* b2 = (const float*)d_in[8];
    float* out = (float*)d_out;

    wavelet_kernel<<<2048, WTH>>>(x1);
    wconv_kernel<<<192 * 32768 / 256, 256>>>(W0);

    static int smem_set = 0;
    if (!smem_set) {
        cudaFuncSetAttribute(gemm_hmma_kernel,
                             cudaFuncAttributeMaxDynamicSharedMemorySize,
                             GEMM_SMEM);
        smem_set = 1;
    }
    dim3 gg(2048 / 128, NSPLIT);   // 16 x 9 = 144 CTAs (one wave)
    gemm_hmma_kernel<<<gg, 256, GEMM_SMEM>>>();

    reduce_kernel<<<2048 * 192 / 256, 256>>>(b0);
    mlp_kernel<<<2048 / MROWS, 256>>>(W1, b1, W2, b2, out);
}